// round 3
// baseline (speedup 1.0000x reference)
#include <cuda_runtime.h>
#include <math.h>

#define N 8192
#define NW (N/32)          // 256 mask words per j-row
#define S1 8               // j-splits, pass 1
#define S2 8               // j-splits, pass 2
#define TJ1 256            // j tile (pass 1, staged in smem)
#define JR1 (N/S1)         // 1024 j per block, pass 1
#define JR2 (N/S2)         // 1024 j per block, pass 2

// -------- scratch (static device globals; no allocation) --------
__device__ float g_y1[N*32];                   // 1 MB
__device__ float g_h[N*32];                    // 1 MB
__device__ float g_y2[N*8];                    // 256 KB
__device__ float g_invrow[N];                  // 32 KB
__device__ unsigned g_mask[(size_t)N*NW];      // 8 MB bitmask: word[j*NW + i/32], bit = lane
__device__ float g_part1[(size_t)S1*N*32];     // 8 MB
__device__ int   g_cnt[S1*N];                  // 256 KB
__device__ float g_part2[(size_t)S2*N*8];      // 2 MB

// ---------------- kernel 1: features + y1 = x@W1 + b1 ----------------
__global__ void feat_kernel(const float4* __restrict__ led, const float* __restrict__ B,
                            const float* __restrict__ emb, const float* __restrict__ W1,
                            const float* __restrict__ b1) {
    __shared__ float sB[48], semb[104], sW1[40*32], sb1[32];
    int t = threadIdx.x;
    if (t < 48)  sB[t]   = B[t];
    if (t < 104) semb[t] = emb[t];
    if (t < 32)  sb1[t]  = b1[t];
    for (int idx = t; idx < 40*32; idx += 256) sW1[idx] = W1[idx];
    __syncthreads();

    int i = blockIdx.x*256 + t;
    float4 p = led[i];
    float x[40];
    #pragma unroll
    for (int f = 0; f < 16; f++) {
        float pr = (p.x*sB[f] + p.y*sB[16+f] + p.z*sB[32+f]) * 6.283185307179586f;
        float sv, cv; sincosf(pr, &sv, &cv);
        x[f] = sv; x[16+f] = cv;
    }
    int fr = (int)p.w;
    #pragma unroll
    for (int e = 0; e < 8; e++) x[32+e] = semb[fr*8 + e];

    #pragma unroll 4
    for (int k = 0; k < 32; k++) {
        float acc = sb1[k];
        #pragma unroll
        for (int d = 0; d < 40; d++) acc = fmaf(x[d], sW1[d*32 + k], acc);
        g_y1[i*32 + k] = acc;
    }
}

// ---------------- kernel 2: pass 1 — masked sum of y1, build bitmask ----------------
__global__ void __launch_bounds__(256) pass1_kernel(const float4* __restrict__ led) {
    __shared__ __align__(16) float s_y[TJ1*32];   // 32 KB
    __shared__ float4 s_pos[TJ1];                 // 4 KB
    int t = threadIdx.x;
    int lane = t & 31;
    int i = blockIdx.x*256 + t;
    int s = blockIdx.y;
    int j0 = s*JR1;
    int iw = i >> 5;

    float4 pi = led[i];
    unsigned long long acc[16];
    #pragma unroll
    for (int k = 0; k < 16; k++) acc[k] = 0ull;
    int cnt = 0;

    for (int tile = 0; tile < JR1/TJ1; tile++) {
        int jt = j0 + tile*TJ1;
        __syncthreads();
        // stage y1 tile: TJ1*32 floats = 2048 float4, 8 per thread
        {
            const float4* src = (const float4*)&g_y1[(size_t)jt*32];
            float4* dst = (float4*)s_y;
            #pragma unroll
            for (int r = 0; r < 8; r++) dst[t + r*256] = src[t + r*256];
            s_pos[t] = led[jt + t];
        }
        __syncthreads();

        for (int jj = 0; jj < TJ1; jj++) {
            float4 pj = s_pos[jj];
            float dx = pi.x - pj.x, dy = pi.y - pj.y, dz = pi.z - pj.z;
            float d2 = fmaf(dx, dx, fmaf(dy, dy, dz*dz));
            bool pred = d2 < 6.25f;
            cnt += pred;
            unsigned w = __ballot_sync(0xffffffffu, pred);
            if (lane == 0) g_mask[(size_t)(jt + jj)*NW + iw] = w;

            unsigned mi = pred ? 0x3f800000u : 0u;
            unsigned long long m64;
            asm("mov.b64 %0, {%1, %1};" : "=l"(m64) : "r"(mi));

            const ulonglong2* yrow = (const ulonglong2*)&s_y[jj*32];
            #pragma unroll
            for (int q = 0; q < 8; q++) {
                ulonglong2 yv = yrow[q];
                asm("fma.rn.f32x2 %0, %1, %2, %0;" : "+l"(acc[2*q])   : "l"(m64), "l"(yv.x));
                asm("fma.rn.f32x2 %0, %1, %2, %0;" : "+l"(acc[2*q+1]) : "l"(m64), "l"(yv.y));
            }
        }
    }
    unsigned long long* dst = (unsigned long long*)&g_part1[((size_t)s*N + i)*32];
    #pragma unroll
    for (int k = 0; k < 16; k++) dst[k] = acc[k];
    g_cnt[s*N + i] = cnt;
}

// ---------------- kernel 3: reduce partials -> h = relu(sum * invrow) ----------------
__global__ void reduce1_kernel() {
    int idx = blockIdx.x*256 + threadIdx.x;   // N*32 threads
    int i = idx >> 5;
    float sum = 0.0f;
    #pragma unroll
    for (int s = 0; s < S1; s++) sum += g_part1[((size_t)s*N)*32 + idx];
    int c = 0;
    #pragma unroll
    for (int s = 0; s < S1; s++) c += g_cnt[s*N + i];
    float inv = 1.0f / ((float)c + 1e-6f);
    float h = sum * inv;
    g_h[idx] = h > 0.0f ? h : 0.0f;
    if ((idx & 31) == 0) g_invrow[i] = inv;
}

// ---------------- kernel 4: y2 = h@W2 + b2 ----------------
__global__ void y2_kernel(const float* __restrict__ W2, const float* __restrict__ b2) {
    __shared__ float sW2[32*8], sb2[8];
    int t = threadIdx.x;
    if (t < 256) sW2[t] = W2[t];
    if (t < 8)   sb2[t] = b2[t];
    __syncthreads();
    int i = blockIdx.x*256 + t;
    float h[32];
    #pragma unroll
    for (int d = 0; d < 32; d++) h[d] = g_h[i*32 + d];
    #pragma unroll
    for (int k = 0; k < 8; k++) {
        float a = sb2[k];
        #pragma unroll
        for (int d = 0; d < 32; d++) a = fmaf(h[d], sW2[d*8 + k], a);
        g_y2[i*8 + k] = a;
    }
}

// ---------------- kernel 5: pass 2 — masked sum of y2 (bitmask reuse) ----------------
__global__ void __launch_bounds__(256) pass2_kernel() {
    __shared__ __align__(16) float s_y[JR2*8];    // 32 KB
    int t = threadIdx.x, lane = t & 31;
    int i = blockIdx.x*256 + t;
    int s = blockIdx.y;
    int j0 = s*JR2;
    int iw = i >> 5;
    {
        const float4* src = (const float4*)&g_y2[(size_t)j0*8];
        float4* dst = (float4*)s_y;
        #pragma unroll
        for (int r = 0; r < 8; r++) dst[t + r*256] = src[t + r*256];
    }
    __syncthreads();

    unsigned long long acc[4] = {0ull, 0ull, 0ull, 0ull};
    for (int jj = 0; jj < JR2; jj++) {
        unsigned w = __ldg(&g_mask[(size_t)(j0 + jj)*NW + iw]);
        unsigned mi = ((w >> lane) & 1u) ? 0x3f800000u : 0u;
        unsigned long long m64;
        asm("mov.b64 %0, {%1, %1};" : "=l"(m64) : "r"(mi));
        const ulonglong2* yrow = (const ulonglong2*)&s_y[jj*8];
        ulonglong2 a = yrow[0], b = yrow[1];
        asm("fma.rn.f32x2 %0, %1, %2, %0;" : "+l"(acc[0]) : "l"(m64), "l"(a.x));
        asm("fma.rn.f32x2 %0, %1, %2, %0;" : "+l"(acc[1]) : "l"(m64), "l"(a.y));
        asm("fma.rn.f32x2 %0, %1, %2, %0;" : "+l"(acc[2]) : "l"(m64), "l"(b.x));
        asm("fma.rn.f32x2 %0, %1, %2, %0;" : "+l"(acc[3]) : "l"(m64), "l"(b.y));
    }
    unsigned long long* dst = (unsigned long long*)&g_part2[((size_t)s*N + i)*8];
    #pragma unroll
    for (int k = 0; k < 4; k++) dst[k] = acc[k];
}

// ---------------- kernel 6: reduce + relu -> out ----------------
__global__ void reduce2_kernel(float* __restrict__ out) {
    int idx = blockIdx.x*256 + threadIdx.x;   // N*8 threads
    int i = idx >> 3;
    float sum = 0.0f;
    #pragma unroll
    for (int s = 0; s < S2; s++) sum += g_part2[((size_t)s*N)*8 + idx];
    float v = sum * g_invrow[i];
    out[idx] = v > 0.0f ? v : 0.0f;
}

// ---------------- launch ----------------
extern "C" void kernel_launch(void* const* d_in, const int* in_sizes, int n_in,
                              void* d_out, int out_size) {
    const float4* led = (const float4*)d_in[0];   // [N,4] pos.xyz + freq
    const float*  B   = (const float*)d_in[1];    // [3,16]
    const float*  emb = (const float*)d_in[2];    // [13,8]
    const float*  W1  = (const float*)d_in[3];    // [40,32]
    const float*  b1  = (const float*)d_in[4];    // [32]
    const float*  W2  = (const float*)d_in[5];    // [32,8]
    const float*  b2  = (const float*)d_in[6];    // [8]
    float* out = (float*)d_out;                   // [N,8] fp32

    feat_kernel<<<32, 256>>>(led, B, emb, W1, b1);
    pass1_kernel<<<dim3(32, S1), 256>>>(led);
    reduce1_kernel<<<N*32/256, 256>>>();
    y2_kernel<<<32, 256>>>(W2, b2);
    pass2_kernel<<<dim3(32, S2), 256>>>();
    reduce2_kernel<<<N*8/256, 256>>>(out);
}

// round 7
// speedup vs baseline: 2.6717x; 2.6717x over previous
#include <cuda_runtime.h>
#include <cuda_bf16.h>
#include <cstdint>
#include <math.h>

#define N 8192
#define S1 8            // j-splits per pass
#define NIB 64          // i-blocks of 128 rows  (64*128 = 8192 = N  ── was the R5 bug)
#define KT 128          // j staged per tile
#define RS 272          // SMEM B row stride bytes (128*2 + 16 pad)

// -------- scratch (static device globals; no allocation) --------
__device__ __nv_bfloat16 g_y1hi[32*N];   // [n][j] 512KB
__device__ __nv_bfloat16 g_y1lo[32*N];
__device__ __nv_bfloat16 g_y2hi[8*N];    // [n][j] 128KB
__device__ __nv_bfloat16 g_y2lo[8*N];
__device__ float g_h[N*32];
__device__ float g_invrow[N];
__device__ float g_part1[(size_t)S1*N*32];   // 8MB
__device__ float g_cnt1[(size_t)S1*N];
__device__ float g_part2[(size_t)S1*N*8];

// ===================== helpers =====================
__device__ __forceinline__ uint32_t smem_u32(const void* p) {
    uint32_t a;
    asm("{ .reg .u64 t; cvta.to.shared.u64 t, %1; cvt.u32.u64 %0, t; }" : "=r"(a) : "l"(p));
    return a;
}
__device__ __forceinline__ uint32_t pack_bf16x2(float lo, float hi) {
    uint32_t r;
    asm("cvt.rn.satfinite.bf16x2.f32 %0, %1, %2;" : "=r"(r) : "f"(hi), "f"(lo));
    return r;
}
#define MMA16816(d, a, b0v, b1v) asm volatile( \
    "mma.sync.aligned.m16n8k16.row.col.f32.bf16.bf16.f32 " \
    "{%0,%1,%2,%3}, {%4,%5,%6,%7}, {%8,%9}, {%0,%1,%2,%3};" \
    : "+f"((d)[0]),"+f"((d)[1]),"+f"((d)[2]),"+f"((d)[3]) \
    : "r"((a)[0]),"r"((a)[1]),"r"((a)[2]),"r"((a)[3]), "r"(b0v),"r"(b1v))
#define LDSM_X4(r0,r1,r2,r3, addr) asm volatile( \
    "ldmatrix.sync.aligned.m8n8.x4.shared.b16 {%0,%1,%2,%3}, [%4];" \
    : "=r"(r0),"=r"(r1),"=r"(r2),"=r"(r3) : "r"(addr))

#define ONESB 0x3f803f80u   // bf16 {1.0, 1.0}

// ---------------- kernel 1: features + y1 = x@W1 + b1, split hi/lo [n][j] ----------------
__global__ void feat_kernel(const float4* __restrict__ led, const float* __restrict__ B,
                            const float* __restrict__ emb, const float* __restrict__ W1,
                            const float* __restrict__ b1) {
    __shared__ float sB[48], semb[104], sW1[40*32], sb1[32];
    int t = threadIdx.x;
    if (t < 48)  sB[t]   = B[t];
    if (t < 104) semb[t] = emb[t];
    if (t < 32)  sb1[t]  = b1[t];
    for (int idx = t; idx < 40*32; idx += 256) sW1[idx] = W1[idx];
    __syncthreads();

    int i = blockIdx.x*256 + t;
    float4 p = led[i];
    float x[40];
    #pragma unroll
    for (int f = 0; f < 16; f++) {
        float pr = (p.x*sB[f] + p.y*sB[16+f] + p.z*sB[32+f]) * 6.283185307179586f;
        float sv, cv; sincosf(pr, &sv, &cv);
        x[f] = sv; x[16+f] = cv;
    }
    int fr = (int)p.w;
    #pragma unroll
    for (int e = 0; e < 8; e++) x[32+e] = semb[fr*8 + e];

    #pragma unroll 4
    for (int k = 0; k < 32; k++) {
        float acc = sb1[k];
        #pragma unroll
        for (int d = 0; d < 40; d++) acc = fmaf(x[d], sW1[d*32 + k], acc);
        __nv_bfloat16 hi = __float2bfloat16(acc);
        __nv_bfloat16 lo = __float2bfloat16(acc - __bfloat162float(hi));
        g_y1hi[k*N + i] = hi;
        g_y1lo[k*N + i] = lo;
    }
}

// ---------------- kernel 2: pass 1 — HMMA masked GEMM (n=32) + counts ----------------
__global__ void __launch_bounds__(256, 1) pass1_mma(const float4* __restrict__ led) {
    __shared__ __align__(16) char sBhi[32*RS];   // 8.5KB
    __shared__ __align__(16) char sBlo[32*RS];
    __shared__ float4 s_pos[KT];

    int t = threadIdx.x, lane = t & 31, wid = t >> 5;
    int ib = blockIdx.x, s = blockIdx.y;
    int q = lane & 3, r = lane >> 2;
    int i0 = ib*128 + wid*16 + r;                 // i1 = i0 + 8
    float4 pi0 = led[i0], pi1 = led[i0 + 8];

    float dacc[4][4] = {};   // n-groups 0..3 (n = 8g + 2q, rows i0/i1)
    float dcnt[4] = {};

    // ldmatrix lane base addrs: sel 0..3 -> (group +0/+1) x (koff 0/16)
    int sel = lane >> 3, lrow = lane & 7;
    uint32_t rowoff = (uint32_t)(((sel >> 1)*8 + lrow)*RS + (sel & 1)*16);
    uint32_t hA = smem_u32(sBhi) + rowoff;            // groups 0,1
    uint32_t hB = smem_u32(sBhi) + 16*RS + rowoff;    // groups 2,3
    uint32_t lA = smem_u32(sBlo) + rowoff;
    uint32_t lB = smem_u32(sBlo) + 16*RS + rowoff;

    for (int tile = 0; tile < 1024/KT; tile++) {
        int j0 = s*1024 + tile*KT;
        __syncthreads();
        // stage B: 32 rows x 256B each for hi and lo (16B chunks)
        #pragma unroll
        for (int c = t; c < 512; c += 256) {
            int n = c >> 4, c16 = c & 15;
            *(uint4*)(sBhi + n*RS + c16*16) = *(const uint4*)(g_y1hi + (size_t)n*N + j0 + c16*8);
            *(uint4*)(sBlo + n*RS + c16*16) = *(const uint4*)(g_y1lo + (size_t)n*N + j0 + c16*8);
        }
        if (t < KT) s_pos[t] = led[j0 + t];
        __syncthreads();

        #pragma unroll
        for (int kc = 0; kc < KT/16; kc++) {
            int jb = kc*16 + 2*q;
            float4 pj0 = s_pos[jb],     pj1 = s_pos[jb + 1];
            float4 pj2 = s_pos[jb + 8], pj3 = s_pos[jb + 9];

            uint32_t a[4];
            {
                float dx, dy, dz, d2;
                #define MASKV(pi, pj, out) \
                    dx = pi.x - pj.x; dy = pi.y - pj.y; dz = pi.z - pj.z; \
                    d2 = fmaf(dx, dx, fmaf(dy, dy, dz*dz)); \
                    float out = (d2 < 6.25f) ? 1.0f : 0.0f;
                MASKV(pi0, pj0, m00) MASKV(pi0, pj1, m01)
                MASKV(pi0, pj2, m02) MASKV(pi0, pj3, m03)
                MASKV(pi1, pj0, m10) MASKV(pi1, pj1, m11)
                MASKV(pi1, pj2, m12) MASKV(pi1, pj3, m13)
                #undef MASKV
                a[0] = pack_bf16x2(m00, m01);
                a[1] = pack_bf16x2(m10, m11);
                a[2] = pack_bf16x2(m02, m03);
                a[3] = pack_bf16x2(m12, m13);
            }

            uint32_t koff = (uint32_t)(kc*32);
            uint32_t h0,h1,h2,h3, h4,h5,h6,h7, l0,l1,l2,l3, l4,l5,l6,l7;
            LDSM_X4(h0,h1,h2,h3, hA + koff);   // b(g0), b(g1)
            LDSM_X4(h4,h5,h6,h7, hB + koff);   // b(g2), b(g3)
            LDSM_X4(l0,l1,l2,l3, lA + koff);
            LDSM_X4(l4,l5,l6,l7, lB + koff);

            MMA16816(dacc[0], a, h0, h1);
            MMA16816(dacc[1], a, h2, h3);
            MMA16816(dacc[2], a, h4, h5);
            MMA16816(dacc[3], a, h6, h7);
            MMA16816(dacc[0], a, l0, l1);
            MMA16816(dacc[1], a, l2, l3);
            MMA16816(dacc[2], a, l4, l5);
            MMA16816(dacc[3], a, l6, l7);
            MMA16816(dcnt,    a, ONESB, ONESB);
        }
    }

    // store partials: D[r=i0][n=8g+2q .. +1], rows i0 and i0+8
    float* d0 = &g_part1[((size_t)s*N + i0)*32];
    float* d1 = d0 + 8*32;
    #pragma unroll
    for (int g = 0; g < 4; g++) {
        *(float2*)(d0 + 8*g + 2*q) = make_float2(dacc[g][0], dacc[g][1]);
        *(float2*)(d1 + 8*g + 2*q) = make_float2(dacc[g][2], dacc[g][3]);
    }
    if (q == 0) {
        g_cnt1[(size_t)s*N + i0]     = dcnt[0];
        g_cnt1[(size_t)s*N + i0 + 8] = dcnt[2];
    }
}

// ---------------- kernel 3: reduce partials -> h, invrow ----------------
__global__ void reduce1_kernel() {
    int idx = blockIdx.x*256 + threadIdx.x;   // N*32
    int i = idx >> 5;
    float sum = 0.0f;
    #pragma unroll
    for (int s = 0; s < S1; s++) sum += g_part1[(size_t)s*N*32 + idx];
    float c = 0.0f;
    #pragma unroll
    for (int s = 0; s < S1; s++) c += g_cnt1[(size_t)s*N + i];
    float inv = 1.0f / (c + 1e-6f);
    float h = sum * inv;
    g_h[idx] = h > 0.0f ? h : 0.0f;
    if ((idx & 31) == 0) g_invrow[i] = inv;
}

// ---------------- kernel 4: y2 = h@W2 + b2, split hi/lo [n][j] ----------------
__global__ void y2_kernel(const float* __restrict__ W2, const float* __restrict__ b2) {
    __shared__ float sW2[32*8], sb2[8];
    int t = threadIdx.x;
    if (t < 256) sW2[t] = W2[t];
    if (t < 8)   sb2[t] = b2[t];
    __syncthreads();
    int idx = blockIdx.x*256 + t;   // N*8
    int i = idx >> 3, k = idx & 7;
    const float4* hrow = (const float4*)&g_h[(size_t)i*32];
    float a = sb2[k];
    #pragma unroll
    for (int p = 0; p < 8; p++) {
        float4 hv = hrow[p];
        a = fmaf(hv.x, sW2[(4*p+0)*8 + k], a);
        a = fmaf(hv.y, sW2[(4*p+1)*8 + k], a);
        a = fmaf(hv.z, sW2[(4*p+2)*8 + k], a);
        a = fmaf(hv.w, sW2[(4*p+3)*8 + k], a);
    }
    __nv_bfloat16 hi = __float2bfloat16(a);
    __nv_bfloat16 lo = __float2bfloat16(a - __bfloat162float(hi));
    g_y2hi[k*N + i] = hi;
    g_y2lo[k*N + i] = lo;
}

// ---------------- kernel 5: pass 2 — HMMA masked GEMM (n=8) ----------------
__global__ void __launch_bounds__(256, 1) pass2_mma(const float4* __restrict__ led) {
    __shared__ __align__(16) char sBhi[8*RS];
    __shared__ __align__(16) char sBlo[8*RS];
    __shared__ float4 s_pos[KT];

    int t = threadIdx.x, lane = t & 31, wid = t >> 5;
    int ib = blockIdx.x, s = blockIdx.y;
    int q = lane & 3, r = lane >> 2;
    int i0 = ib*128 + wid*16 + r;
    float4 pi0 = led[i0], pi1 = led[i0 + 8];

    float dacc[4] = {};

    // x4: sel0/1 -> hi tiles (koff 0/16), sel2/3 -> lo tiles
    int sel = lane >> 3, lrow = lane & 7;
    uint32_t base = (sel < 2) ? smem_u32(sBhi) : smem_u32(sBlo);
    uint32_t bAddr = base + (uint32_t)(lrow*RS + (sel & 1)*16);

    for (int tile = 0; tile < 1024/KT; tile++) {
        int j0 = s*1024 + tile*KT;
        __syncthreads();
        // stage B: 8 rows x 256B, hi + lo = 256 chunks of 16B
        if (t < 128) {
            int c = t;
            int n = c >> 4, c16 = c & 15;
            *(uint4*)(sBhi + n*RS + c16*16) = *(const uint4*)(g_y2hi + (size_t)n*N + j0 + c16*8);
            *(uint4*)(sBlo + n*RS + c16*16) = *(const uint4*)(g_y2lo + (size_t)n*N + j0 + c16*8);
        } else {
            s_pos[t - 128] = led[j0 + (t - 128)];
        }
        __syncthreads();

        #pragma unroll
        for (int kc = 0; kc < KT/16; kc++) {
            int jb = kc*16 + 2*q;
            float4 pj0 = s_pos[jb],     pj1 = s_pos[jb + 1];
            float4 pj2 = s_pos[jb + 8], pj3 = s_pos[jb + 9];

            uint32_t a[4];
            {
                float dx, dy, dz, d2;
                #define MASKV(pi, pj, out) \
                    dx = pi.x - pj.x; dy = pi.y - pj.y; dz = pi.z - pj.z; \
                    d2 = fmaf(dx, dx, fmaf(dy, dy, dz*dz)); \
                    float out = (d2 < 6.25f) ? 1.0f : 0.0f;
                MASKV(pi0, pj0, m00) MASKV(pi0, pj1, m01)
                MASKV(pi0, pj2, m02) MASKV(pi0, pj3, m03)
                MASKV(pi1, pj0, m10) MASKV(pi1, pj1, m11)
                MASKV(pi1, pj2, m12) MASKV(pi1, pj3, m13)
                #undef MASKV
                a[0] = pack_bf16x2(m00, m01);
                a[1] = pack_bf16x2(m10, m11);
                a[2] = pack_bf16x2(m02, m03);
                a[3] = pack_bf16x2(m12, m13);
            }

            uint32_t h0, h1, l0, l1;
            LDSM_X4(h0, h1, l0, l1, bAddr + (uint32_t)(kc*32));
            MMA16816(dacc, a, h0, h1);
            MMA16816(dacc, a, l0, l1);
        }
    }

    float* d0 = &g_part2[((size_t)s*N + i0)*8];
    *(float2*)(d0 + 2*q)        = make_float2(dacc[0], dacc[1]);
    *(float2*)(d0 + 8*8 + 2*q)  = make_float2(dacc[2], dacc[3]);   // row i0+8
}

// ---------------- kernel 6: reduce + relu -> out ----------------
__global__ void reduce2_kernel(float* __restrict__ out) {
    int idx = blockIdx.x*256 + threadIdx.x;   // N*8
    int i = idx >> 3;
    float sum = 0.0f;
    #pragma unroll
    for (int s = 0; s < S1; s++) sum += g_part2[(size_t)s*N*8 + idx];
    float v = sum * g_invrow[i];
    out[idx] = v > 0.0f ? v : 0.0f;
}

// ---------------- launch ----------------
extern "C" void kernel_launch(void* const* d_in, const int* in_sizes, int n_in,
                              void* d_out, int out_size) {
    const float4* led = (const float4*)d_in[0];
    const float*  B   = (const float*)d_in[1];
    const float*  emb = (const float*)d_in[2];
    const float*  W1  = (const float*)d_in[3];
    const float*  b1  = (const float*)d_in[4];
    const float*  W2  = (const float*)d_in[5];
    const float*  b2  = (const float*)d_in[6];
    float* out = (float*)d_out;

    feat_kernel<<<32, 256>>>(led, B, emb, W1, b1);
    pass1_mma<<<dim3(NIB, S1), 256>>>(led);
    reduce1_kernel<<<N*32/256, 256>>>();
    y2_kernel<<<N*8/256, 256>>>(W2, b2);
    pass2_mma<<<dim3(NIB, S1), 256>>>(led);
    reduce2_kernel<<<N*8/256, 256>>>(out);
}

// round 8
// speedup vs baseline: 2.8440x; 1.0645x over previous
#include <cuda_runtime.h>
#include <cuda_bf16.h>
#include <cstdint>
#include <math.h>

#define N 8192
#define S1 4            // j-splits per pass
#define NIB 64          // i-blocks of 128 rows
#define JR (N/S1)       // 2048 j per CTA
#define KT 256          // j staged per tile
#define NT (JR/KT)      // 8 tiles
#define RS 528          // SMEM B row stride bytes (256*2 + 16 pad)

// -------- scratch (static device globals; no allocation) --------
__device__ __nv_bfloat16 g_y1hi[32*N];   // [n][j]
__device__ __nv_bfloat16 g_y1lo[32*N];
__device__ __nv_bfloat16 g_y2hi[8*N];    // [n][j]
__device__ __nv_bfloat16 g_y2lo[8*N];
__device__ float g_h[N*32];
__device__ float g_invrow[N];
__device__ float g_part1[(size_t)S1*N*32];   // 4MB
__device__ float g_cnt1[(size_t)S1*N];
__device__ float g_part2[(size_t)S1*N*8];

// ===================== helpers =====================
__device__ __forceinline__ uint32_t smem_u32(const void* p) {
    uint32_t a;
    asm("{ .reg .u64 t; cvta.to.shared.u64 t, %1; cvt.u32.u64 %0, t; }" : "=r"(a) : "l"(p));
    return a;
}
__device__ __forceinline__ uint32_t pack_bf16x2(float lo, float hi) {
    uint32_t r;
    asm("cvt.rn.satfinite.bf16x2.f32 %0, %1, %2;" : "=r"(r) : "f"(hi), "f"(lo));
    return r;
}
__device__ __forceinline__ unsigned long long pk2(float lo, float hi) {
    unsigned long long r;
    asm("mov.b64 %0, {%1, %2};" : "=l"(r) : "f"(lo), "f"(hi));
    return r;
}
__device__ __forceinline__ unsigned long long bc2(float x) { return pk2(x, x); }
__device__ __forceinline__ unsigned long long mul2(unsigned long long a, unsigned long long b) {
    unsigned long long r; asm("mul.rn.f32x2 %0,%1,%2;" : "=l"(r) : "l"(a), "l"(b)); return r;
}
__device__ __forceinline__ unsigned long long fma2(unsigned long long a, unsigned long long b, unsigned long long c) {
    unsigned long long r; asm("fma.rn.f32x2 %0,%1,%2,%3;" : "=l"(r) : "l"(a), "l"(b), "l"(c)); return r;
}
__device__ __forceinline__ unsigned long long add2(unsigned long long a, unsigned long long b) {
    unsigned long long r; asm("add.rn.f32x2 %0,%1,%2;" : "=l"(r) : "l"(a), "l"(b)); return r;
}
// masks for a j-pair: (dot > thr) ? 1.0 : 0.0, packed to bf16x2
__device__ __forceinline__ uint32_t setpack(unsigned long long dot, unsigned long long thr) {
    float dl, dh, tl, th, ml, mh;
    asm("mov.b64 {%0, %1}, %2;" : "=f"(dl), "=f"(dh) : "l"(dot));
    asm("mov.b64 {%0, %1}, %2;" : "=f"(tl), "=f"(th) : "l"(thr));
    asm("set.gt.f32.f32 %0, %1, %2;" : "=f"(ml) : "f"(dl), "f"(tl));
    asm("set.gt.f32.f32 %0, %1, %2;" : "=f"(mh) : "f"(dh), "f"(th));
    return pack_bf16x2(ml, mh);
}
#define MMA16816(d, a, b0v, b1v) asm volatile( \
    "mma.sync.aligned.m16n8k16.row.col.f32.bf16.bf16.f32 " \
    "{%0,%1,%2,%3}, {%4,%5,%6,%7}, {%8,%9}, {%0,%1,%2,%3};" \
    : "+f"((d)[0]),"+f"((d)[1]),"+f"((d)[2]),"+f"((d)[3]) \
    : "r"((a)[0]),"r"((a)[1]),"r"((a)[2]),"r"((a)[3]), "r"(b0v),"r"(b1v))
#define LDSM_X4(r0,r1,r2,r3, addr) asm volatile( \
    "ldmatrix.sync.aligned.m8n8.x4.shared.b16 {%0,%1,%2,%3}, [%4];" \
    : "=r"(r0),"=r"(r1),"=r"(r2),"=r"(r3) : "r"(addr))

#define ONESB 0x3f803f80u   // bf16 {1.0, 1.0}

// build packed pair entry from two consecutive points
__device__ __forceinline__ ulonglong4 make_pair(float4 a, float4 b) {
    float ca = fmaf(a.x, a.x, fmaf(a.y, a.y, a.z*a.z));
    float cb = fmaf(b.x, b.x, fmaf(b.y, b.y, b.z*b.z));
    ulonglong4 r;
    r.x = pk2(a.x, b.x);
    r.y = pk2(a.y, b.y);
    r.z = pk2(a.z, b.z);
    r.w = pk2((ca - 6.25f)*0.5f, (cb - 6.25f)*0.5f);
    return r;
}

// ---------------- kernel 1: features + y1 = x@W1 + b1, split hi/lo [n][j] ----------------
__global__ void feat_kernel(const float4* __restrict__ led, const float* __restrict__ B,
                            const float* __restrict__ emb, const float* __restrict__ W1,
                            const float* __restrict__ b1) {
    __shared__ float sB[48], semb[104], sW1[40*32], sb1[32];
    int t = threadIdx.x;
    if (t < 48)  sB[t]   = B[t];
    if (t < 104) semb[t] = emb[t];
    if (t < 32)  sb1[t]  = b1[t];
    for (int idx = t; idx < 40*32; idx += 256) sW1[idx] = W1[idx];
    __syncthreads();

    int i = blockIdx.x*256 + t;
    float4 p = led[i];
    float x[40];
    #pragma unroll
    for (int f = 0; f < 16; f++) {
        float pr = (p.x*sB[f] + p.y*sB[16+f] + p.z*sB[32+f]) * 6.283185307179586f;
        float sv, cv; sincosf(pr, &sv, &cv);
        x[f] = sv; x[16+f] = cv;
    }
    int fr = (int)p.w;
    #pragma unroll
    for (int e = 0; e < 8; e++) x[32+e] = semb[fr*8 + e];

    #pragma unroll 4
    for (int k = 0; k < 32; k++) {
        float acc = sb1[k];
        #pragma unroll
        for (int d = 0; d < 40; d++) acc = fmaf(x[d], sW1[d*32 + k], acc);
        __nv_bfloat16 hi = __float2bfloat16(acc);
        __nv_bfloat16 lo = __float2bfloat16(acc - __bfloat162float(hi));
        g_y1hi[k*N + i] = hi;
        g_y1lo[k*N + i] = lo;
    }
}

// ---------------- kernel 2: pass 1 — HMMA masked GEMM (n=32) + counts ----------------
__global__ void __launch_bounds__(256, 2) pass1_mma(const float4* __restrict__ led) {
    __shared__ __align__(16) char sBhi[32*RS];      // 16.5KB
    __shared__ __align__(16) char sBlo[32*RS];      // 16.5KB
    __shared__ __align__(16) ulonglong4 s_pj[KT/2]; // 4KB packed j-pairs

    int t = threadIdx.x, lane = t & 31, wid = t >> 5;
    int ib = blockIdx.x, s = blockIdx.y;
    int q = lane & 3, r = lane >> 2;
    int i0 = ib*128 + wid*16 + r;                 // rows i0, i0+8
    float4 pi0 = led[i0], pi1 = led[i0 + 8];

    unsigned long long px0 = bc2(pi0.x), py0 = bc2(pi0.y), pz0 = bc2(pi0.z);
    unsigned long long px1 = bc2(pi1.x), py1 = bc2(pi1.y), pz1 = bc2(pi1.z);
    unsigned long long tc0 = bc2(0.5f*fmaf(pi0.x, pi0.x, fmaf(pi0.y, pi0.y, pi0.z*pi0.z)));
    unsigned long long tc1 = bc2(0.5f*fmaf(pi1.x, pi1.x, fmaf(pi1.y, pi1.y, pi1.z*pi1.z)));

    float dacc[4][4] = {};   // n-groups 0..3 (n = 8g + 2q), rows i0/i1
    float dcnt[4] = {};

    int sel = lane >> 3, lrow = lane & 7;
    uint32_t rowoff = (uint32_t)(((sel >> 1)*8 + lrow)*RS + (sel & 1)*16);
    uint32_t hA = smem_u32(sBhi) + rowoff;            // n-groups 0,1
    uint32_t hB = smem_u32(sBhi) + 16*RS + rowoff;    // n-groups 2,3
    uint32_t lA = smem_u32(sBlo) + rowoff;
    uint32_t lB = smem_u32(sBlo) + 16*RS + rowoff;

    for (int tile = 0; tile < NT; tile++) {
        int j0 = s*JR + tile*KT;
        __syncthreads();
        // stage B: 32 rows x 512B (32 chunks of 16B) for hi and lo
        #pragma unroll
        for (int c = t; c < 1024; c += 256) {
            int n = c >> 5, ch = c & 31;
            *(uint4*)(sBhi + n*RS + ch*16) = *(const uint4*)(g_y1hi + (size_t)n*N + j0 + ch*8);
            *(uint4*)(sBlo + n*RS + ch*16) = *(const uint4*)(g_y1lo + (size_t)n*N + j0 + ch*8);
        }
        if (t < KT/2) s_pj[t] = make_pair(led[j0 + 2*t], led[j0 + 2*t + 1]);
        __syncthreads();

        #pragma unroll
        for (int kc = 0; kc < KT/16; kc++) {
            int p0 = kc*8 + q;          // j-pair (jb, jb+1)
            ulonglong4 P0 = s_pj[p0];
            ulonglong4 P1 = s_pj[p0 + 4];   // j-pair (jb+8, jb+9)

            uint32_t a[4];
            {
                unsigned long long d00 = fma2(pz0, P0.z, fma2(py0, P0.y, mul2(px0, P0.x)));
                unsigned long long d10 = fma2(pz1, P0.z, fma2(py1, P0.y, mul2(px1, P0.x)));
                unsigned long long t00 = add2(P0.w, tc0);
                unsigned long long t10 = add2(P0.w, tc1);
                a[0] = setpack(d00, t00);
                a[1] = setpack(d10, t10);
                unsigned long long d01 = fma2(pz0, P1.z, fma2(py0, P1.y, mul2(px0, P1.x)));
                unsigned long long d11 = fma2(pz1, P1.z, fma2(py1, P1.y, mul2(px1, P1.x)));
                unsigned long long t01 = add2(P1.w, tc0);
                unsigned long long t11 = add2(P1.w, tc1);
                a[2] = setpack(d01, t01);
                a[3] = setpack(d11, t11);
            }

            uint32_t koff = (uint32_t)(kc*32);
            uint32_t h0,h1,h2,h3, h4,h5,h6,h7, l0,l1,l2,l3, l4,l5,l6,l7;
            LDSM_X4(h0,h1,h2,h3, hA + koff);
            LDSM_X4(h4,h5,h6,h7, hB + koff);
            LDSM_X4(l0,l1,l2,l3, lA + koff);
            LDSM_X4(l4,l5,l6,l7, lB + koff);

            MMA16816(dacc[0], a, h0, h1);
            MMA16816(dacc[1], a, h2, h3);
            MMA16816(dacc[2], a, h4, h5);
            MMA16816(dacc[3], a, h6, h7);
            MMA16816(dacc[0], a, l0, l1);
            MMA16816(dacc[1], a, l2, l3);
            MMA16816(dacc[2], a, l4, l5);
            MMA16816(dacc[3], a, l6, l7);
            MMA16816(dcnt,    a, ONESB, ONESB);
        }
    }

    float* d0 = &g_part1[((size_t)s*N + i0)*32];
    float* d1 = d0 + 8*32;
    #pragma unroll
    for (int g = 0; g < 4; g++) {
        *(float2*)(d0 + 8*g + 2*q) = make_float2(dacc[g][0], dacc[g][1]);
        *(float2*)(d1 + 8*g + 2*q) = make_float2(dacc[g][2], dacc[g][3]);
    }
    if (q == 0) {
        g_cnt1[(size_t)s*N + i0]     = dcnt[0];
        g_cnt1[(size_t)s*N + i0 + 8] = dcnt[2];
    }
}

// ---------------- kernel 3: reduce partials -> h, invrow ----------------
__global__ void reduce1_kernel() {
    int idx = blockIdx.x*256 + threadIdx.x;   // N*32
    int i = idx >> 5;
    float sum = 0.0f;
    #pragma unroll
    for (int s = 0; s < S1; s++) sum += g_part1[(size_t)s*N*32 + idx];
    float c = 0.0f;
    #pragma unroll
    for (int s = 0; s < S1; s++) c += g_cnt1[(size_t)s*N + i];
    float inv = 1.0f / (c + 1e-6f);
    float h = sum * inv;
    g_h[idx] = h > 0.0f ? h : 0.0f;
    if ((idx & 31) == 0) g_invrow[i] = inv;
}

// ---------------- kernel 4: y2 = h@W2 + b2, split hi/lo [n][j] ----------------
__global__ void y2_kernel(const float* __restrict__ W2, const float* __restrict__ b2) {
    __shared__ float sW2[32*8], sb2[8];
    int t = threadIdx.x;
    if (t < 256) sW2[t] = W2[t];
    if (t < 8)   sb2[t] = b2[t];
    __syncthreads();
    int idx = blockIdx.x*256 + t;   // N*8
    int i = idx >> 3, k = idx & 7;
    const float4* hrow = (const float4*)&g_h[(size_t)i*32];
    float a = sb2[k];
    #pragma unroll
    for (int p = 0; p < 8; p++) {
        float4 hv = hrow[p];
        a = fmaf(hv.x, sW2[(4*p+0)*8 + k], a);
        a = fmaf(hv.y, sW2[(4*p+1)*8 + k], a);
        a = fmaf(hv.z, sW2[(4*p+2)*8 + k], a);
        a = fmaf(hv.w, sW2[(4*p+3)*8 + k], a);
    }
    __nv_bfloat16 hi = __float2bfloat16(a);
    __nv_bfloat16 lo = __float2bfloat16(a - __bfloat162float(hi));
    g_y2hi[k*N + i] = hi;
    g_y2lo[k*N + i] = lo;
}

// ---------------- kernel 5: pass 2 — HMMA masked GEMM (n=8) ----------------
__global__ void __launch_bounds__(256, 2) pass2_mma(const float4* __restrict__ led) {
    __shared__ __align__(16) char sBhi[8*RS];
    __shared__ __align__(16) char sBlo[8*RS];
    __shared__ __align__(16) ulonglong4 s_pj[KT/2];

    int t = threadIdx.x, lane = t & 31, wid = t >> 5;
    int ib = blockIdx.x, s = blockIdx.y;
    int q = lane & 3, r = lane >> 2;
    int i0 = ib*128 + wid*16 + r;
    float4 pi0 = led[i0], pi1 = led[i0 + 8];

    unsigned long long px0 = bc2(pi0.x), py0 = bc2(pi0.y), pz0 = bc2(pi0.z);
    unsigned long long px1 = bc2(pi1.x), py1 = bc2(pi1.y), pz1 = bc2(pi1.z);
    unsigned long long tc0 = bc2(0.5f*fmaf(pi0.x, pi0.x, fmaf(pi0.y, pi0.y, pi0.z*pi0.z)));
    unsigned long long tc1 = bc2(0.5f*fmaf(pi1.x, pi1.x, fmaf(pi1.y, pi1.y, pi1.z*pi1.z)));

    float dacc[4] = {};

    // x4: sel0/1 -> hi (koff 0/16), sel2/3 -> lo
    int sel = lane >> 3, lrow = lane & 7;
    uint32_t base = (sel < 2) ? smem_u32(sBhi) : smem_u32(sBlo);
    uint32_t bAddr = base + (uint32_t)(lrow*RS + (sel & 1)*16);

    for (int tile = 0; tile < NT; tile++) {
        int j0 = s*JR + tile*KT;
        __syncthreads();
        // stage B: 8 rows x 512B hi + lo = 512 chunks of 16B; 2 per thread
        {
            int n = t >> 5, ch = t & 31;
            *(uint4*)(sBhi + n*RS + ch*16) = *(const uint4*)(g_y2hi + (size_t)n*N + j0 + ch*8);
            *(uint4*)(sBlo + n*RS + ch*16) = *(const uint4*)(g_y2lo + (size_t)n*N + j0 + ch*8);
        }
        if (t < KT/2) s_pj[t] = make_pair(led[j0 + 2*t], led[j0 + 2*t + 1]);
        __syncthreads();

        #pragma unroll
        for (int kc = 0; kc < KT/16; kc++) {
            int p0 = kc*8 + q;
            ulonglong4 P0 = s_pj[p0];
            ulonglong4 P1 = s_pj[p0 + 4];

            uint32_t a[4];
            {
                unsigned long long d00 = fma2(pz0, P0.z, fma2(py0, P0.y, mul2(px0, P0.x)));
                unsigned long long d10 = fma2(pz1, P0.z, fma2(py1, P0.y, mul2(px1, P0.x)));
                unsigned long long t00 = add2(P0.w, tc0);
                unsigned long long t10 = add2(P0.w, tc1);
                a[0] = setpack(d00, t00);
                a[1] = setpack(d10, t10);
                unsigned long long d01 = fma2(pz0, P1.z, fma2(py0, P1.y, mul2(px0, P1.x)));
                unsigned long long d11 = fma2(pz1, P1.z, fma2(py1, P1.y, mul2(px1, P1.x)));
                unsigned long long t01 = add2(P1.w, tc0);
                unsigned long long t11 = add2(P1.w, tc1);
                a[2] = setpack(d01, t01);
                a[3] = setpack(d11, t11);
            }

            uint32_t h0, h1, l0, l1;
            LDSM_X4(h0, h1, l0, l1, bAddr + (uint32_t)(kc*32));
            MMA16816(dacc, a, h0, h1);
            MMA16816(dacc, a, l0, l1);
        }
    }

    float* d0 = &g_part2[((size_t)s*N + i0)*8];
    *(float2*)(d0 + 2*q)        = make_float2(dacc[0], dacc[1]);
    *(float2*)(d0 + 8*8 + 2*q)  = make_float2(dacc[2], dacc[3]);   // row i0+8
}

// ---------------- kernel 6: reduce + relu -> out ----------------
__global__ void reduce2_kernel(float* __restrict__ out) {
    int idx = blockIdx.x*256 + threadIdx.x;   // N*8
    int i = idx >> 3;
    float sum = 0.0f;
    #pragma unroll
    for (int s = 0; s < S1; s++) sum += g_part2[(size_t)s*N*8 + idx];
    float v = sum * g_invrow[i];
    out[idx] = v > 0.0f ? v : 0.0f;
}

// ---------------- launch ----------------
extern "C" void kernel_launch(void* const* d_in, const int* in_sizes, int n_in,
                              void* d_out, int out_size) {
    const float4* led = (const float4*)d_in[0];
    const float*  B   = (const float*)d_in[1];
    const float*  emb = (const float*)d_in[2];
    const float*  W1  = (const float*)d_in[3];
    const float*  b1  = (const float*)d_in[4];
    const float*  W2  = (const float*)d_in[5];
    const float*  b2  = (const float*)d_in[6];
    float* out = (float*)d_out;

    feat_kernel<<<32, 256>>>(led, B, emb, W1, b1);
    pass1_mma<<<dim3(NIB, S1), 256>>>(led);
    reduce1_kernel<<<N*32/256, 256>>>();
    y2_kernel<<<N*8/256, 256>>>(W2, b2);
    pass2_mma<<<dim3(NIB, S1), 256>>>(led);
    reduce2_kernel<<<N*8/256, 256>>>(out);
}